// round 11
// baseline (speedup 1.0000x reference)
#include <cuda_runtime.h>

// MaxAssigner2D, two-phase:
//   Phase 1 (streaming): xc[p] = max over 32 channels of x[p*32 .. p*32+31]
//       (R2/R8 proven form - 84.1us, ~6.3 TB/s, frozen)
//   Phase 2 (stencil):   out[b,h,w] = max over taps
//       {(0,0),(-1,0),(-2,0),(0,-1),(0,-2),(-1,-1),(-2,-2)} of xc[b,h+dh,w+dw]
//       persistent single-wave grid, 2-deep software pipeline
//   (out-of-image taps contribute 0, matching the reference zero pad)

#define BATCH 16
#define HGT   512
#define WID   512
#define CH    32
#define NPIX  (BATCH * HGT * WID)   // 4,194,304

__device__ float g_xc[NPIX];        // 16 MB scratch (allocation-free)

// ---------------- Phase 1: channel-max, pure streaming (frozen) ------------
#define K1_NT      256
#define K1_BLOCKS  2048
#define K1_GROUPS  (K1_BLOCKS * K1_NT / 8)        // 65,536 pixel groups / sweep
#define K1_ITERS   (NPIX / K1_GROUPS)             // 64, exact

__global__ void __launch_bounds__(K1_NT)
chanmax_kernel(const float* __restrict__ x)
{
    const int tid = blockIdx.x * K1_NT + threadIdx.x;
    const int gid = tid >> 3;           // pixel-group id
    const int chq = tid & 7;            // which float4 of 32 channels

    #pragma unroll 8
    for (int it = 0; it < K1_ITERS; it++) {
        const int p = it * K1_GROUPS + gid;
        const float4 d = __ldg((const float4*)(x + (size_t)p * CH) + chq);
        float v = fmaxf(fmaxf(d.x, d.y), fmaxf(d.z, d.w));
        v = fmaxf(v, __shfl_xor_sync(0xffffffffu, v, 1));
        v = fmaxf(v, __shfl_xor_sync(0xffffffffu, v, 2));
        v = fmaxf(v, __shfl_xor_sync(0xffffffffu, v, 4));
        if (chq == 0) g_xc[p] = v;
    }
}

// ---------------- Phase 2: persistent pipelined 7-tap stencil --------------
#define K2_NT     256
#define K2_BLOCKS (148 * 6)                 // 888: one fully-resident wave
#define K2_STRIDE (K2_BLOCKS * K2_NT)       // 227,328
#define NQ        (NPIX / 4)                // 1,048,576 output quads

struct Stage {
    float4 a2, a1, a0;    // rows h, h-1, h-2 (cols 4q..4q+3)
    float2 l2, l0;        // cols 4q-2,4q-1 of rows h, h-2
    float  l1;            // col 4q-1 of row h-1
};

__device__ __forceinline__ void load_stage(const float* __restrict__ xc,
                                           int p, Stage& S)
{
    const int q = p & 127;
    const int h = (p >> 7) & 511;
    const float* base = xc + ((size_t)p << 2);

    const float4 z4 = make_float4(0.f, 0.f, 0.f, 0.f);
    const float2 z2 = make_float2(0.f, 0.f);

    S.a2 = __ldg((const float4*)base);
    S.l2 = q ? __ldg((const float2*)(base - 2)) : z2;
    S.a1 = (h >= 1) ? __ldg((const float4*)(base - WID)) : z4;
    S.l1 = (h >= 1 && q) ? __ldg(base - WID - 1) : 0.f;
    S.a0 = (h >= 2) ? __ldg((const float4*)(base - 2 * WID)) : z4;
    S.l0 = (h >= 2 && q) ? __ldg((const float2*)(base - 2 * WID - 2)) : z2;
}

__device__ __forceinline__ float4 compute_stage(const Stage& S)
{
    // taps per col j: (0,j)(0,j-1)(0,j-2) | (-1,j)(-1,j-1) | (-2,j)(-2,j-2)
    float4 m;
    m.x = fmaxf(fmaxf(fmaxf(S.a2.x, S.l2.y), fmaxf(S.l2.x, S.a1.x)),
                fmaxf(S.l1,    fmaxf(S.a0.x, S.l0.x)));
    m.y = fmaxf(fmaxf(fmaxf(S.a2.y, S.a2.x), fmaxf(S.l2.y, S.a1.y)),
                fmaxf(S.a1.x, fmaxf(S.a0.y, S.l0.y)));
    m.z = fmaxf(fmaxf(fmaxf(S.a2.z, S.a2.y), fmaxf(S.a2.x, S.a1.z)),
                fmaxf(S.a1.y, fmaxf(S.a0.z, S.a0.x)));
    m.w = fmaxf(fmaxf(fmaxf(S.a2.w, S.a2.z), fmaxf(S.a2.y, S.a1.w)),
                fmaxf(S.a1.z, fmaxf(S.a0.w, S.a0.y)));
    return m;
}

__global__ void __launch_bounds__(K2_NT, 6)
stencil_kernel(const float* __restrict__ xc, float* __restrict__ out)
{
    int p = blockIdx.x * K2_NT + threadIdx.x;

    Stage A;
    load_stage(xc, p, A);          // prologue load

    while (true) {
        const int pn = p + K2_STRIDE;
        const bool more = (pn < NQ);
        Stage B;
        if (more) load_stage(xc, pn, B);   // next-stage loads issued BEFORE
        ((float4*)out)[p] = compute_stage(A);  // computing/storing current
        if (!more) break;
        A = B;
        p = pn;
    }
}

extern "C" void kernel_launch(void* const* d_in, const int* in_sizes, int n_in,
                              void* d_out, int out_size)
{
    (void)in_sizes; (void)n_in; (void)out_size;
    const float* x = (const float*)d_in[0];
    float* out = (float*)d_out;

    float* xc_ptr;
    cudaGetSymbolAddress((void**)&xc_ptr, g_xc);

    chanmax_kernel<<<K1_BLOCKS, K1_NT>>>(x);
    stencil_kernel<<<K2_BLOCKS, K2_NT>>>(xc_ptr, out);
}

// round 12
// speedup vs baseline: 1.0222x; 1.0222x over previous
#include <cuda_runtime.h>

// MaxAssigner2D, two-phase with PDL overlap:
//   Phase 1 (streaming): xc[p] = max over 32 channels of x[p*32 .. p*32+31]
//       (R2 proven form, + early programmatic-launch trigger)
//   Phase 2 (stencil):   out[b,h,w] = max over taps
//       {(0,0),(-1,0),(-2,0),(0,-1),(0,-2),(-1,-1),(-2,-2)} of xc[b,h+dh,w+dw]
//       (R7 proven form, + grid-dependency sync; launched with PDL so its
//        blocks pre-stage on SMs while phase 1 drains)
//   (out-of-image taps contribute 0, matching the reference zero pad)

#define BATCH 16
#define HGT   512
#define WID   512
#define CH    32
#define NPIX  (BATCH * HGT * WID)   // 4,194,304

__device__ float g_xc[NPIX];        // 16 MB scratch (allocation-free)

// ---------------- Phase 1: channel-max, pure streaming (frozen form) -------
#define K1_NT      256
#define K1_BLOCKS  2048
#define K1_GROUPS  (K1_BLOCKS * K1_NT / 8)        // 65,536 pixel groups / sweep
#define K1_ITERS   (NPIX / K1_GROUPS)             // 64, exact

__global__ void __launch_bounds__(K1_NT)
chanmax_kernel(const float* __restrict__ x)
{
    // Allow the dependent stencil kernel to begin scheduling immediately;
    // it self-gates on cudaGridDependencySynchronize() before touching g_xc.
    cudaTriggerProgrammaticLaunchCompletion();

    const int tid = blockIdx.x * K1_NT + threadIdx.x;
    const int gid = tid >> 3;           // pixel-group id
    const int chq = tid & 7;            // which float4 of 32 channels

    #pragma unroll 8
    for (int it = 0; it < K1_ITERS; it++) {
        const int p = it * K1_GROUPS + gid;
        const float4 d = __ldg((const float4*)(x + (size_t)p * CH) + chq);
        float v = fmaxf(fmaxf(d.x, d.y), fmaxf(d.z, d.w));
        v = fmaxf(v, __shfl_xor_sync(0xffffffffu, v, 1));
        v = fmaxf(v, __shfl_xor_sync(0xffffffffu, v, 2));
        v = fmaxf(v, __shfl_xor_sync(0xffffffffu, v, 4));
        if (chq == 0) g_xc[p] = v;
    }
}

// ---------------- Phase 2: direct-load 7-tap stencil (frozen form + PDL) ---
#define K2_NT     256
#define K2_BLOCKS (NPIX / 4 / K2_NT)    // 4096

__global__ void __launch_bounds__(K2_NT)
stencil_kernel(const float* __restrict__ xc, float* __restrict__ out)
{
    // Prologue (no dependence on phase-1 output): index math.
    const int p   = blockIdx.x * K2_NT + threadIdx.x;  // quad id
    const int q   = p & 127;            // quad within row (cols 4q..4q+3)
    const int h   = (p >> 7) & 511;     // image row
    const float* base = xc + ((size_t)p << 2);   // &xc[img][h][4q]

    // Wait here (HW wait) until phase 1 has fully completed + flushed.
    cudaGridDependencySynchronize();

    // Row h: always valid.
    const float4 a2 = __ldg((const float4*)base);
    float2 l2 = make_float2(0.f, 0.f);           // cols 4q-2, 4q-1 of row h
    if (q) l2 = __ldg((const float2*)(base - 2));

    // Rows h-1, h-2: may be above the image (zero pad).
    float4 a1 = make_float4(0.f, 0.f, 0.f, 0.f);
    float4 a0 = make_float4(0.f, 0.f, 0.f, 0.f);
    float  l1 = 0.f;                             // col 4q-1 of row h-1
    float2 l0 = make_float2(0.f, 0.f);           // cols 4q-2, 4q-1 of row h-2
    if (h >= 1) {
        a1 = __ldg((const float4*)(base - WID));
        if (q) l1 = __ldg(base - WID - 1);
    }
    if (h >= 2) {
        a0 = __ldg((const float4*)(base - 2 * WID));
        if (q) l0 = __ldg((const float2*)(base - 2 * WID - 2));
    }

    // taps per output col j: (0,j)(0,j-1)(0,j-2) | (-1,j)(-1,j-1) | (-2,j)(-2,j-2)
    float4 m;
    m.x = fmaxf(fmaxf(fmaxf(a2.x, l2.y), fmaxf(l2.x, a1.x)),
                fmaxf(l1,   fmaxf(a0.x, l0.x)));
    m.y = fmaxf(fmaxf(fmaxf(a2.y, a2.x), fmaxf(l2.y, a1.y)),
                fmaxf(a1.x, fmaxf(a0.y, l0.y)));
    m.z = fmaxf(fmaxf(fmaxf(a2.z, a2.y), fmaxf(a2.x, a1.z)),
                fmaxf(a1.y, fmaxf(a0.z, a0.x)));
    m.w = fmaxf(fmaxf(fmaxf(a2.w, a2.z), fmaxf(a2.y, a1.w)),
                fmaxf(a1.z, fmaxf(a0.w, a0.y)));

    ((float4*)out)[p] = m;
}

extern "C" void kernel_launch(void* const* d_in, const int* in_sizes, int n_in,
                              void* d_out, int out_size)
{
    (void)in_sizes; (void)n_in; (void)out_size;
    const float* x = (const float*)d_in[0];
    float* out = (float*)d_out;

    float* xc_ptr;
    cudaGetSymbolAddress((void**)&xc_ptr, g_xc);

    chanmax_kernel<<<K1_BLOCKS, K1_NT>>>(x);

    // Launch stencil with programmatic dependent launch: its blocks may be
    // scheduled while chanmax drains; correctness is guaranteed by the
    // cudaGridDependencySynchronize() inside the kernel.
    cudaLaunchAttribute attr[1];
    attr[0].id = cudaLaunchAttributeProgrammaticStreamSerialization;
    attr[0].val.programmaticStreamSerializationAllowed = 1;

    cudaLaunchConfig_t cfg = {};
    cfg.gridDim  = dim3(K2_BLOCKS, 1, 1);
    cfg.blockDim = dim3(K2_NT, 1, 1);
    cfg.dynamicSmemBytes = 0;
    cfg.stream = 0;               // legacy default stream (same as <<<>>>)
    cfg.attrs = attr;
    cfg.numAttrs = 1;

    cudaLaunchKernelEx(&cfg, stencil_kernel, (const float*)xc_ptr, out);
}

// round 13
// speedup vs baseline: 1.0424x; 1.0198x over previous
#include <cuda_runtime.h>

// MaxAssigner2D, fully fused single kernel with per-strip flag handoff:
//   Block b streams channel-max of its contiguous 4-row strip into g_xc
//   (proven R2 loop body, only the pixel mapping is strip-contiguous),
//   publishes flag[b], waits for flag[b-1] (halo rows), then applies the
//   7-tap stencil {(0,0),(-1,0),(-2,0),(0,-1),(0,-2),(-1,-1),(-2,-2)}
//   to its own 4 rows (out-of-image taps = 0, matching the zero pad).

#define BATCH 16
#define HGT   512
#define WID   512
#define CH    32
#define NPIX  (BATCH * HGT * WID)   // 4,194,304

#define NT    256
#define RPB   4                     // rows per block
#define PPB   (RPB * WID)           // 2048 pixels per strip
#define NBLK  (NPIX / PPB)          // 2048 blocks
#define ITERS (PPB / (NT / 8))      // 64, exact (32 pixel-groups per block)
#define BPI   (HGT / RPB)           // 128 blocks per image
#define NQUAD (WID / 4)             // 128

__device__ float g_xc[NPIX];        // 16 MB scratch
__device__ int   g_flag[NBLK];      // strip-ready flags (zero-init; self-resetting)

__global__ void __launch_bounds__(NT)
fused_kernel(const float* __restrict__ x, float* __restrict__ out)
{
    const int t   = threadIdx.x;
    const int b   = blockIdx.x;
    const int g   = t >> 3;           // pixel-group within block (0..31)
    const int chq = t & 7;            // float4 within 32 channels

    // ---- streaming channel-max of own 4-row strip (R2 body, strip mapping) ----
    const size_t pix0 = (size_t)b * PPB;
    const float4* src = (const float4*)(x + pix0 * CH) + chq;
    float* dst = g_xc + pix0;

    #pragma unroll 8
    for (int it = 0; it < ITERS; it++) {
        const int p = it * 32 + g;
        const float4 d = __ldg(src + (size_t)p * (CH / 4));
        float v = fmaxf(fmaxf(d.x, d.y), fmaxf(d.z, d.w));
        v = fmaxf(v, __shfl_xor_sync(0xffffffffu, v, 1));
        v = fmaxf(v, __shfl_xor_sync(0xffffffffu, v, 2));
        v = fmaxf(v, __shfl_xor_sync(0xffffffffu, v, 4));
        if (chq == 0) dst[p] = v;
    }

    // ---- publish own strip, then acquire predecessor's (halo rows) ----------
    __threadfence();                      // make own xc stores visible gpu-wide
    __syncthreads();                      // all threads' fences complete
    if (t == 0) {
        atomicExch(&g_flag[b], 1);        // publish BEFORE waiting: no chains
        if ((b % BPI) != 0) {
            // need rows 4b-1, 4b-2 from block b-1 (same image)
            while (atomicAdd(&g_flag[b - 1], 0) == 0) { }
            atomicExch(&g_flag[b - 1], 0);   // reset for next graph replay
            __threadfence();                 // acquire: invalidate L1 before halo reads
        } else if (b > 0) {
            atomicExch(&g_flag[b - 1], 0);   // never waited on; reset (race benign)
        }
    }
    __syncthreads();

    // ---- stencil own 4 rows (512 quads, 2 per thread; R7 verified body) -----
    const int img = b / BPI;
    const int hh  = (b % BPI) * RPB;
    const float* xc_img = g_xc + (size_t)img * HGT * WID;
    float4* out_img = (float4*)(out + (size_t)img * HGT * WID);

    #pragma unroll
    for (int i = 0; i < 2; i++) {
        const int qq = i * NT + t;        // 0..511
        const int r  = qq >> 7;           // 0..3
        const int q  = qq & 127;
        const int h  = hh + r;
        const float* base = xc_img + (size_t)h * WID + 4 * q;

        const float4 a2 = __ldg((const float4*)base);
        float2 l2 = make_float2(0.f, 0.f);
        if (q) l2 = __ldg((const float2*)(base - 2));

        float4 a1 = make_float4(0.f, 0.f, 0.f, 0.f);
        float4 a0 = make_float4(0.f, 0.f, 0.f, 0.f);
        float  l1 = 0.f;
        float2 l0 = make_float2(0.f, 0.f);
        if (h >= 1) {
            a1 = __ldg((const float4*)(base - WID));
            if (q) l1 = __ldg(base - WID - 1);
        }
        if (h >= 2) {
            a0 = __ldg((const float4*)(base - 2 * WID));
            if (q) l0 = __ldg((const float2*)(base - 2 * WID - 2));
        }

        float4 m;
        m.x = fmaxf(fmaxf(fmaxf(a2.x, l2.y), fmaxf(l2.x, a1.x)),
                    fmaxf(l1,   fmaxf(a0.x, l0.x)));
        m.y = fmaxf(fmaxf(fmaxf(a2.y, a2.x), fmaxf(l2.y, a1.y)),
                    fmaxf(a1.x, fmaxf(a0.y, l0.y)));
        m.z = fmaxf(fmaxf(fmaxf(a2.z, a2.y), fmaxf(a2.x, a1.z)),
                    fmaxf(a1.y, fmaxf(a0.z, a0.x)));
        m.w = fmaxf(fmaxf(fmaxf(a2.w, a2.z), fmaxf(a2.y, a1.w)),
                    fmaxf(a1.z, fmaxf(a0.w, a0.y)));

        out_img[(size_t)h * NQUAD + q] = m;
    }
}

extern "C" void kernel_launch(void* const* d_in, const int* in_sizes, int n_in,
                              void* d_out, int out_size)
{
    (void)in_sizes; (void)n_in; (void)out_size;
    const float* x = (const float*)d_in[0];
    float* out = (float*)d_out;

    fused_kernel<<<NBLK, NT>>>(x, out);
}

// round 14
// speedup vs baseline: 1.0661x; 1.0228x over previous
#include <cuda_runtime.h>

// MaxAssigner2D, fused single kernel, smem-resident xc + halo handoff:
//   Block b streams channel-max of its 4-row strip into SMEM (bottom 2 rows
//   also to the gmem halo buffer for block b+1), publishes flag[b], waits on
//   flag[b-1], then applies the 7-tap stencil
//   {(0,0),(-1,0),(-2,0),(0,-1),(0,-2),(-1,-1),(-2,-2)}  (out-of-image = 0).

#define BATCH 16
#define HGT   512
#define WID   512
#define CH    32
#define NPIX  (BATCH * HGT * WID)   // 4,194,304

#define NT    256
#define RPB   4                     // rows per block
#define PPB   (RPB * WID)           // 2048 pixels per strip
#define NBLK  (NPIX / PPB)          // 2048 blocks
#define ITERS (PPB / (NT / 8))      // 64, exact
#define BPI   (HGT / RPB)           // 128 blocks per image
#define NQUAD (WID / 4)             // 128
#define DATA0 4                     // first data col in smem row (16B aligned)
#define SW    520                   // smem row stride (floats)

__device__ float g_halo[NBLK * 2 * WID];   // 8 MB: per strip, its rows 2,3
__device__ int   g_flag[NBLK];             // strip-ready flags (self-resetting)

__global__ void __launch_bounds__(NT)
fused_kernel(const float* __restrict__ x, float* __restrict__ out)
{
    __shared__ float s[RPB * SW];   // 8,320 B: own strip's xc, zero left halo

    const int t   = threadIdx.x;
    const int b   = blockIdx.x;
    const int g   = t >> 3;           // pixel-group within block (0..31)
    const int chq = t & 7;            // float4 within 32 channels

    // zero left-halo cols (DATA0-2, DATA0-1) of all 4 smem rows
    if (t < RPB * 2) s[(t >> 1) * SW + 2 + (t & 1)] = 0.0f;

    // ---- streaming channel-max of own strip (R13 body; store -> smem) ------
    const size_t pix0 = (size_t)b * PPB;
    const float4* src = (const float4*)(x + pix0 * CH) + chq;
    float* halo_out = g_halo + (size_t)b * 2 * WID;

    #pragma unroll 8
    for (int it = 0; it < ITERS; it++) {
        const int p = it * 32 + g;                  // 0..2047, row-major
        const float4 d = __ldg(src + (size_t)p * (CH / 4));
        float v = fmaxf(fmaxf(d.x, d.y), fmaxf(d.z, d.w));
        v = fmaxf(v, __shfl_xor_sync(0xffffffffu, v, 1));
        v = fmaxf(v, __shfl_xor_sync(0xffffffffu, v, 2));
        v = fmaxf(v, __shfl_xor_sync(0xffffffffu, v, 4));
        if (chq == 0) {
            s[(p >> 9) * SW + DATA0 + (p & 511)] = v;
            if (p >= 2 * WID) halo_out[p - 2 * WID] = v;   // rows 2,3 -> successor
        }
    }

    // ---- publish own halo, then acquire predecessor's ----------------------
    __threadfence();
    __syncthreads();
    if (t == 0) {
        atomicExch(&g_flag[b], 1);            // publish BEFORE waiting
        if ((b % BPI) != 0) {
            while (atomicAdd(&g_flag[b - 1], 0) == 0) { }
            atomicExch(&g_flag[b - 1], 0);    // reset for next graph replay
            __threadfence();                  // acquire
        } else if (b > 0) {
            atomicExch(&g_flag[b - 1], 0);    // never waited on; reset
        }
    }
    __syncthreads();

    // ---- stencil own 4 rows (512 quads, 2/thread) ---------------------------
    const int  img     = b / BPI;
    const int  hh      = (b % BPI) * RPB;
    const bool hasPrev = (b % BPI) != 0;
    const float* hal   = g_halo + (size_t)(b - 1) * 2 * WID;  // prev rows 2,3
    float4* out_img    = (float4*)(out + (size_t)img * HGT * WID);

    const float4 z4 = make_float4(0.f, 0.f, 0.f, 0.f);
    const float2 z2 = make_float2(0.f, 0.f);

    #pragma unroll
    for (int i = 0; i < 2; i++) {
        const int qq = i * NT + t;        // 0..511
        const int r  = qq >> 7;           // 0..3 (warp-uniform)
        const int q  = qq & 127;
        const int h  = hh + r;

        // row h: own smem (left halo cols are zero-padded, no predicates)
        const float* pA = s + r * SW + DATA0 + 4 * q;
        const float4 a  = *(const float4*)pA;
        const float  la1 = pA[-1], la2 = pA[-2];

        float4 bv; float lb1;             // row h-1
        float4 cv; float lc1, lc2;        // row h-2
        if (r >= 2) {
            const float* pB = pA - SW;
            const float* pC = pB - SW;
            bv = *(const float4*)pB; lb1 = pB[-1];
            cv = *(const float4*)pC; lc1 = pC[-1]; lc2 = pC[-2];
        } else if (r == 1) {
            const float* pB = s + DATA0 + 4 * q;      // own row 0
            bv = *(const float4*)pB; lb1 = pB[-1];
            if (hasPrev) {                             // prev row 3 = halo slot 1
                const float* C = hal + WID;
                cv = __ldg((const float4*)(C + 4 * q));
                const float2 lc = q ? __ldg((const float2*)(C + 4 * q - 2)) : z2;
                lc2 = lc.x; lc1 = lc.y;
            } else { cv = z4; lc1 = lc2 = 0.f; }
        } else {                                       // r == 0
            if (hasPrev) {
                const float* B = hal + WID;            // prev row 3 (h-1)
                const float* C = hal;                  // prev row 2 (h-2)
                bv = __ldg((const float4*)(B + 4 * q));
                lb1 = q ? __ldg(B + 4 * q - 1) : 0.f;
                cv = __ldg((const float4*)(C + 4 * q));
                const float2 lc = q ? __ldg((const float2*)(C + 4 * q - 2)) : z2;
                lc2 = lc.x; lc1 = lc.y;
            } else { bv = z4; cv = z4; lb1 = lc1 = lc2 = 0.f; }
        }

        // taps per col j: (0,j)(0,j-1)(0,j-2) | (-1,j)(-1,j-1) | (-2,j)(-2,j-2)
        float4 m;
        m.x = fmaxf(fmaxf(fmaxf(a.x, la1), fmaxf(la2, bv.x)),
                    fmaxf(lb1,  fmaxf(cv.x, lc2)));
        m.y = fmaxf(fmaxf(fmaxf(a.y, a.x), fmaxf(la1, bv.y)),
                    fmaxf(bv.x, fmaxf(cv.y, lc1)));
        m.z = fmaxf(fmaxf(fmaxf(a.z, a.y), fmaxf(a.x, bv.z)),
                    fmaxf(bv.y, fmaxf(cv.z, cv.x)));
        m.w = fmaxf(fmaxf(fmaxf(a.w, a.z), fmaxf(a.y, bv.w)),
                    fmaxf(bv.z, fmaxf(cv.w, cv.y)));

        out_img[(size_t)h * NQUAD + q] = m;
    }
}

extern "C" void kernel_launch(void* const* d_in, const int* in_sizes, int n_in,
                              void* d_out, int out_size)
{
    (void)in_sizes; (void)n_in; (void)out_size;
    const float* x = (const float*)d_in[0];
    float* out = (float*)d_out;

    fused_kernel<<<NBLK, NT>>>(x, out);
}